// round 11
// baseline (speedup 1.0000x reference)
#include <cuda_runtime.h>
#include <cuda_bf16.h>
#include <math.h>

#define T_STEPS 100000
#define S_DIM   200
#define N_DIM   215

// ---- device scratch (static; no runtime allocation) ----
__device__ float g_pre_f[T_STEPS * S_DIM];
__device__ float g_pre_i[T_STEPS * S_DIM];
__device__ float g_cand [T_STEPS * S_DIM];
__device__ float g_sfinal[S_DIM];

// ---- helpers ----
__device__ __forceinline__ unsigned smem_u32(const void* p) {
    unsigned a;
    asm("{ .reg .u64 t; cvta.to.shared.u64 t, %1; cvt.u32.u64 %0, t; }"
        : "=r"(a) : "l"(p));
    return a;
}
__device__ __forceinline__ unsigned mapa_u32(unsigned a, unsigned rank) {
    unsigned d;
    asm("mapa.shared::cluster.u32 %0, %1, %2;" : "=r"(d) : "r"(a), "r"(rank));
    return d;
}
// atomic add into cluster-window smem (local or remote CTA), no return value
__device__ __forceinline__ void red_add_cluster_f32(unsigned addr, float v) {
    asm volatile("red.relaxed.cluster.shared::cluster.add.f32 [%0], %1;"
                 :: "r"(addr), "f"(v) : "memory");
}
__device__ __forceinline__ unsigned long long pack2(float x, float y) {
    unsigned long long r;
    asm("mov.b64 %0, {%1, %2};" : "=l"(r) : "f"(x), "f"(y));
    return r;
}
__device__ __forceinline__ float2 unpack2(unsigned long long v) {
    float2 f;
    asm("mov.b64 {%0, %1}, %2;" : "=f"(f.x), "=f"(f.y) : "l"(v));
    return f;
}
#define FMA2(acc, a, b) \
    asm("fma.rn.f32x2 %0, %1, %2, %0;" : "+l"(acc) : "l"(a), "l"(b))
#define ADD2(out, a, b) \
    asm("add.rn.f32x2 %0, %1, %2;" : "=l"(out) : "l"(a), "l"(b))

#define CLUSTER_ARRIVE() \
    asm volatile("barrier.cluster.arrive.aligned;" ::: "memory")
#define CLUSTER_WAIT() \
    asm volatile("barrier.cluster.wait.aligned;" ::: "memory")

// ============================================================
// Phase 1: the three track GEMMs. grid (3125,3), block 256.
// ============================================================
#define TILE_T 32
#define KCHUNK 43   // 5*43 = 215

__global__ __launch_bounds__(256) void pre_kernel(
    const float* __restrict__ track,
    const float* __restrict__ Wf, const float* __restrict__ bf,
    const float* __restrict__ Wi, const float* __restrict__ bi,
    const float* __restrict__ Wc, const float* __restrict__ bc)
{
    __shared__ float sW[KCHUNK * S_DIM];
    __shared__ float sT[TILE_T * KCHUNK];
    const int mat = blockIdx.y;
    const int t0  = blockIdx.x * TILE_T;
    const int tid = threadIdx.x;
    const float* W   = (mat == 0) ? Wf : (mat == 1) ? Wi : Wc;
    const float* bia = (mat == 0) ? bf : (mat == 1) ? bi : bc;
    float* out       = (mat == 0) ? g_pre_f : (mat == 1) ? g_pre_i : g_cand;

    float acc[TILE_T];
    #pragma unroll
    for (int i = 0; i < TILE_T; i++) acc[i] = 0.0f;

    for (int c = 0; c < 5; c++) {
        const int k0 = c * KCHUNK;
        for (int idx = tid; idx < KCHUNK * S_DIM; idx += 256) {
            int r = idx / S_DIM, col = idx - r * S_DIM;
            sW[idx] = W[(k0 + r) * S_DIM + col];
        }
        for (int idx = tid; idx < TILE_T * KCHUNK; idx += 256) {
            int tt = idx / KCHUNK, kk = idx - tt * KCHUNK;
            sT[idx] = track[(t0 + tt) * N_DIM + k0 + kk];
        }
        __syncthreads();
        if (tid < S_DIM) {
            for (int kk = 0; kk < KCHUNK; kk++) {
                float wv = sW[kk * S_DIM + tid];
                #pragma unroll
                for (int tt = 0; tt < TILE_T; tt++)
                    acc[tt] = fmaf(sT[tt * KCHUNK + kk], wv, acc[tt]);
            }
        }
        __syncthreads();
    }
    if (tid < S_DIM) {
        float bv = bia[tid];
        #pragma unroll 4
        for (int tt = 0; tt < TILE_T; tt++) {
            float v = acc[tt] + bv;
            if (mat == 2) v = tanhf(v);
            out[(t0 + tt) * S_DIM + tid] = v;
        }
    }
}

// ============================================================
// Phase 2: sequential scan. 2-CTA cluster, 416 threads/CTA.
// Triple-buffered red-add exchange, ONE cluster barrier per step:
//   step t: matvec reads s_buf[(t+2)%3] (complete state),
//           both CTAs red.add their gate contribution into
//           s_buf[t%3][j] of BOTH CTAs (local + remote DSMEM red),
//           owners zero s_buf[(t+1)%3][j],
//           one barrier.cluster -> s_buf[t%3] IS the new state.
// No syncthreads, no update phase on the critical path.
// rank0: u = s_old * sigmoid(pre_f + s@Wf_s)
// rank1: v = sigmoid(pre_i + s@Wi_s) * cand
// ============================================================
__global__ void __cluster_dims__(2, 1, 1) __launch_bounds__(416, 1)
scan_kernel(const float* __restrict__ Wf, const float* __restrict__ Wi,
            const float* __restrict__ state0)
{
    __shared__ __align__(16) float s_buf[3][S_DIM];

    const int tid = threadIdx.x;
    unsigned rank;
    asm("mov.u32 %0, %%cluster_ctarank;" : "=r"(rank));
    const unsigned peerR = rank ^ 1u;

    const bool act = (tid < 400);
    const int  j   = act ? (tid >> 1) : 0;   // output column
    const int  h   = tid & 1;                // k-half
    const bool own = act && (h == 0);

    // ---- load this CTA's recurrent matrix into registers ----
    const float* W = (rank == 0) ? Wf : Wi;  // rows [215,415) = recurrent part
    const int kbase = N_DIM + h * 100;
    unsigned long long w[50];
    #pragma unroll
    for (int i = 0; i < 50; i++) {
        float a = act ? W[(kbase + 2 * i    ) * S_DIM + j] : 0.0f;
        float b = act ? W[(kbase + 2 * i + 1) * S_DIM + j] : 0.0f;
        w[i] = pack2(a, b);
    }

    // init: buffer 2 holds state0; buffers 0,1 zeroed
    if (own) {
        s_buf[2][j] = state0[j];
        s_buf[0][j] = 0.0f;
        s_buf[1][j] = 0.0f;
    }
    __syncthreads();
    CLUSTER_ARRIVE();
    CLUSTER_WAIT();

    // cluster-window addresses of column j in buffer 0 (stride 800 B/buffer)
    const unsigned lcol = mapa_u32(smem_u32(&s_buf[0][0]) + 4u * j, rank);
    const unsigned pcol = mapa_u32(smem_u32(&s_buf[0][0]) + 4u * j, peerR);

    const float* pre = (rank == 0) ? g_pre_f : g_pre_i;
    float p_cur = 0.0f, c_cur = 0.0f;
    if (own) {
        p_cur = __ldcg(pre + j);
        if (rank == 1) c_cur = __ldcg(g_cand + j);
    }

    int ir = 2, ia = 0, iz = 1;   // read / accumulate / zero buffer indices

    for (int t = 0; t < T_STEPS; t++) {
        // prefetch next step's streams (hides DRAM latency)
        float p_next = 0.0f, c_next = 0.0f;
        if (own) {
            int tn = (t + 1 < T_STEPS) ? (t + 1) : (T_STEPS - 1);
            p_next = __ldcg(pre + tn * S_DIM + j);
            if (rank == 1) c_next = __ldcg(g_cand + tn * S_DIM + j);
        }

        const float* srow = s_buf[ir];
        float s_old = (own && rank == 0) ? srow[j] : 0.0f;

        // ---- matvec: 100 MACs/thread as 50 packed f32x2 FMAs ----
        unsigned long long a0 = 0ull, a1 = 0ull;
        const ulonglong2* s4 = (const ulonglong2*)srow + h * 25;
        #pragma unroll
        for (int i = 0; i < 25; i++) {
            ulonglong2 sv = s4[i];
            FMA2(a0, w[2 * i    ], sv.x);
            FMA2(a1, w[2 * i + 1], sv.y);
        }
        unsigned long long r01;
        ADD2(r01, a0, a1);
        float2 f = unpack2(r01);
        float zp = f.x + f.y;
        float z  = zp + __shfl_xor_sync(0xFFFFFFFFu, zp, 1);

        if (own) {
            z += p_cur;
            float g = __fdividef(1.0f, 1.0f + __expf(-z));
            float contrib = (rank == 0) ? (s_old * g) : (g * c_cur);
            // accumulate into BOTH CTAs' new-state buffer (atomic adds)
            unsigned off = (unsigned)(ia * (S_DIM * 4));
            red_add_cluster_f32(lcol + off, contrib);
            red_add_cluster_f32(pcol + off, contrib);
            // zero the buffer that will accumulate at step t+1
            s_buf[iz][j] = 0.0f;
        }

        // ONE sync per step: orders all local+remote reds and the zeroing
        CLUSTER_ARRIVE();
        CLUSTER_WAIT();

        // rotate buffers: (read, accum, zero) <- (accum, zero, read)
        int tmp = ir; ir = ia; ia = iz; iz = tmp;
        p_cur = p_next; c_cur = c_next;
    }

    if (rank == 0 && own) g_sfinal[j] = s_buf[ir][j];
    CLUSTER_ARRIVE();
    CLUSTER_WAIT();
}

// ============================================================
// Phase 3: output head. 1 block, 256 threads.
// ============================================================
__global__ __launch_bounds__(256) void head_kernel(
    const float* __restrict__ W1, const float* __restrict__ b1,
    const float* __restrict__ W2, const float* __restrict__ b2,
    float* __restrict__ out)
{
    __shared__ float s_s[S_DIM], s_h[S_DIM], s_red[256];
    const int tid = threadIdx.x;
    if (tid < S_DIM) s_s[tid] = g_sfinal[tid];
    __syncthreads();

    if (tid < S_DIM) {
        float a = b1[tid];
        for (int k = 0; k < S_DIM; k++) a = fmaf(s_s[k], W1[k * S_DIM + tid], a);
        s_h[tid] = fmaxf(a, 0.0f);
    }
    __syncthreads();
    float h2 = 0.0f;
    if (tid < S_DIM) {
        float a = b2[tid];
        for (int k = 0; k < S_DIM; k++) a = fmaf(s_h[k], W2[k * S_DIM + tid], a);
        h2 = fmaxf(a, 0.0f);
    }
    s_red[tid] = (tid < S_DIM) ? h2 : -1e30f;
    __syncthreads();
    for (int s = 128; s > 0; s >>= 1) {
        if (tid < s) s_red[tid] = fmaxf(s_red[tid], s_red[tid + s]);
        __syncthreads();
    }
    float m = s_red[0];
    __syncthreads();
    s_red[tid] = (tid < S_DIM) ? expf(h2 - m) : 0.0f;
    __syncthreads();
    for (int s = 128; s > 0; s >>= 1) {
        if (tid < s) s_red[tid] += s_red[tid + s];
        __syncthreads();
    }
    float lse = logf(s_red[0]);
    if (tid < S_DIM) out[tid] = h2 - m - lse;
}

// ============================================================
extern "C" void kernel_launch(void* const* d_in, const int* in_sizes, int n_in,
                              void* d_out, int out_size) {
    const float* track  = (const float*)d_in[0];
    const float* state0 = (const float*)d_in[1];
    const float* Wf     = (const float*)d_in[2];
    const float* bf     = (const float*)d_in[3];
    const float* Wi     = (const float*)d_in[4];
    const float* bi     = (const float*)d_in[5];
    const float* Wc     = (const float*)d_in[6];
    const float* bc     = (const float*)d_in[7];
    const float* W1     = (const float*)d_in[8];
    const float* b1     = (const float*)d_in[9];
    const float* W2     = (const float*)d_in[10];
    const float* b2     = (const float*)d_in[11];
    float* out = (float*)d_out;

    dim3 g(T_STEPS / TILE_T, 3);
    pre_kernel<<<g, 256>>>(track, Wf, bf, Wi, bi, Wc, bc);
    scan_kernel<<<2, 416>>>(Wf, Wi, state0);
    head_kernel<<<1, 256>>>(W1, b1, W2, b2, out);
}

// round 12
// speedup vs baseline: 1.0294x; 1.0294x over previous
#include <cuda_runtime.h>
#include <cuda_bf16.h>
#include <math.h>

#define T_STEPS 100000
#define S_DIM   200
#define N_DIM   215

// ---- device scratch (static; no runtime allocation) ----
__device__ float g_pre_f[T_STEPS * S_DIM];
__device__ float g_pre_i[T_STEPS * S_DIM];
__device__ float g_cand [T_STEPS * S_DIM];
__device__ float g_sfinal[S_DIM];

// ---- helpers ----
__device__ __forceinline__ unsigned smem_u32(const void* p) {
    unsigned a;
    asm("{ .reg .u64 t; cvta.to.shared.u64 t, %1; cvt.u32.u64 %0, t; }"
        : "=r"(a) : "l"(p));
    return a;
}
__device__ __forceinline__ unsigned mapa_u32(unsigned a, unsigned rank) {
    unsigned d;
    asm("mapa.shared::cluster.u32 %0, %1, %2;" : "=r"(d) : "r"(a), "r"(rank));
    return d;
}
__device__ __forceinline__ void st_shared_cluster_f32(unsigned addr, float v) {
    asm volatile("st.shared::cluster.f32 [%0], %1;"
                 :: "r"(addr), "f"(v) : "memory");
}
__device__ __forceinline__ unsigned long long pack2(float x, float y) {
    unsigned long long r;
    asm("mov.b64 %0, {%1, %2};" : "=l"(r) : "f"(x), "f"(y));
    return r;
}
__device__ __forceinline__ float2 unpack2(unsigned long long v) {
    float2 f;
    asm("mov.b64 {%0, %1}, %2;" : "=f"(f.x), "=f"(f.y) : "l"(v));
    return f;
}
#define FMA2(acc, a, b) \
    asm("fma.rn.f32x2 %0, %1, %2, %0;" : "+l"(acc) : "l"(a), "l"(b))
#define ADD2(out, a, b) \
    asm("add.rn.f32x2 %0, %1, %2;" : "=l"(out) : "l"(a), "l"(b))

#define CLUSTER_ARRIVE() \
    asm volatile("barrier.cluster.arrive.aligned;" ::: "memory")
#define CLUSTER_WAIT() \
    asm volatile("barrier.cluster.wait.aligned;" ::: "memory")

// ============================================================
// Phase 1: the three track GEMMs. grid (3125,3), block 256.
// ============================================================
#define TILE_T 32
#define KCHUNK 43   // 5*43 = 215

__global__ __launch_bounds__(256) void pre_kernel(
    const float* __restrict__ track,
    const float* __restrict__ Wf, const float* __restrict__ bf,
    const float* __restrict__ Wi, const float* __restrict__ bi,
    const float* __restrict__ Wc, const float* __restrict__ bc)
{
    __shared__ float sW[KCHUNK * S_DIM];
    __shared__ float sT[TILE_T * KCHUNK];
    const int mat = blockIdx.y;
    const int t0  = blockIdx.x * TILE_T;
    const int tid = threadIdx.x;
    const float* W   = (mat == 0) ? Wf : (mat == 1) ? Wi : Wc;
    const float* bia = (mat == 0) ? bf : (mat == 1) ? bi : bc;
    float* out       = (mat == 0) ? g_pre_f : (mat == 1) ? g_pre_i : g_cand;

    float acc[TILE_T];
    #pragma unroll
    for (int i = 0; i < TILE_T; i++) acc[i] = 0.0f;

    for (int c = 0; c < 5; c++) {
        const int k0 = c * KCHUNK;
        for (int idx = tid; idx < KCHUNK * S_DIM; idx += 256) {
            int r = idx / S_DIM, col = idx - r * S_DIM;
            sW[idx] = W[(k0 + r) * S_DIM + col];
        }
        for (int idx = tid; idx < TILE_T * KCHUNK; idx += 256) {
            int tt = idx / KCHUNK, kk = idx - tt * KCHUNK;
            sT[idx] = track[(t0 + tt) * N_DIM + k0 + kk];
        }
        __syncthreads();
        if (tid < S_DIM) {
            for (int kk = 0; kk < KCHUNK; kk++) {
                float wv = sW[kk * S_DIM + tid];
                #pragma unroll
                for (int tt = 0; tt < TILE_T; tt++)
                    acc[tt] = fmaf(sT[tt * KCHUNK + kk], wv, acc[tt]);
            }
        }
        __syncthreads();
    }
    if (tid < S_DIM) {
        float bv = bia[tid];
        #pragma unroll 4
        for (int tt = 0; tt < TILE_T; tt++) {
            float v = acc[tt] + bv;
            if (mat == 2) v = tanhf(v);
            out[(t0 + tt) * S_DIM + tid] = v;
        }
    }
}

// ============================================================
// Phase 2: sequential scan. 2-CTA cluster, 416 threads/CTA.
// Split-pipelined matvec:
//   s_t = U_t + V_t (own contribution + peer contribution).
//   z = W^T U_t (A-pass, LOCAL data, runs BEFORE the wait,
//       overlapping peer skew + barrier release)
//     + W^T V_t (B-pass, peer data, after the wait).
// Loop: A -> WAIT -> B -> gate -> store local+remote[p^1]
//       -> syncthreads -> ARRIVE.
// Double-buffered by iteration parity; exchange primitives are
// exactly R7's proven remote st.shared::cluster + barrier.cluster.
// rank0 contribution: U = s_old * sigmoid(pre_f + z)
// rank1 contribution: V = sigmoid(pre_i + z) * cand
// ============================================================
__global__ void __cluster_dims__(2, 1, 1) __launch_bounds__(416, 1)
scan_kernel(const float* __restrict__ Wf, const float* __restrict__ Wi,
            const float* __restrict__ state0)
{
    __shared__ __align__(16) float s_loc[2][S_DIM];   // my contributions
    __shared__ __align__(16) float s_rem[2][S_DIM];   // peer contributions

    const int tid = threadIdx.x;
    unsigned rank;
    asm("mov.u32 %0, %%cluster_ctarank;" : "=r"(rank));
    const unsigned peerR = rank ^ 1u;

    const bool act = (tid < 400);
    const int  j   = act ? (tid >> 1) : 0;   // output column
    const int  h   = tid & 1;                // k-half
    const bool own = act && (h == 0);

    // ---- load this CTA's recurrent matrix into registers ----
    const float* W = (rank == 0) ? Wf : Wi;  // rows [215,415) = recurrent part
    const int kbase = N_DIM + h * 100;
    unsigned long long w[50];
    #pragma unroll
    for (int i = 0; i < 50; i++) {
        float a = act ? W[(kbase + 2 * i    ) * S_DIM + j] : 0.0f;
        float b = act ? W[(kbase + 2 * i + 1) * S_DIM + j] : 0.0f;
        w[i] = pack2(a, b);
    }

    // init: s_0 = state0 + 0  (U_0 = state0, V_0 = 0)
    if (own) {
        s_loc[0][j] = state0[j];
        s_loc[1][j] = 0.0f;
        s_rem[0][j] = 0.0f;
        s_rem[1][j] = 0.0f;
    }
    __syncthreads();
    CLUSTER_ARRIVE();                 // phase 0: init published

    // remote addresses of peer's s_rem[b][j] for my column
    const unsigned pr0 = mapa_u32(smem_u32(&s_rem[0][own ? j : 0]), peerR);
    const unsigned pr1 = mapa_u32(smem_u32(&s_rem[1][own ? j : 0]), peerR);

    const float* pre = (rank == 0) ? g_pre_f : g_pre_i;
    float p_cur = 0.0f, c_cur = 0.0f;
    if (own) {
        p_cur = __ldcg(pre + j);
        if (rank == 1) c_cur = __ldcg(g_cand + j);
    }

    for (int t = 0; t < T_STEPS; t++) {
        const int p = t & 1;

        // prefetch next step's streams (hides DRAM latency)
        float p_next = 0.0f, c_next = 0.0f;
        if (own) {
            int tn = (t + 1 < T_STEPS) ? (t + 1) : (T_STEPS - 1);
            p_next = __ldcg(pre + tn * S_DIM + j);
            if (rank == 1) c_next = __ldcg(g_cand + tn * S_DIM + j);
        }

        // ---- A-pass: W^T U_t on LOCAL data, before the wait ----
        unsigned long long aA0 = 0ull, aA1 = 0ull;
        {
            const ulonglong2* s4 = (const ulonglong2*)s_loc[p] + h * 25;
            #pragma unroll
            for (int i = 0; i < 25; i++) {
                ulonglong2 sv = s4[i];
                FMA2(aA0, w[2 * i    ], sv.x);
                FMA2(aA1, w[2 * i + 1], sv.y);
            }
        }

        // wait for the peer's contribution V_t to land
        CLUSTER_WAIT();

        // ---- B-pass: W^T V_t on peer data ----
        unsigned long long aB0 = 0ull, aB1 = 0ull;
        {
            const ulonglong2* s4 = (const ulonglong2*)s_rem[p] + h * 25;
            #pragma unroll
            for (int i = 0; i < 25; i++) {
                ulonglong2 sv = s4[i];
                FMA2(aB0, w[2 * i    ], sv.x);
                FMA2(aB1, w[2 * i + 1], sv.y);
            }
        }

        unsigned long long r0, r1, r2;
        ADD2(r0, aA0, aB0);
        ADD2(r1, aA1, aB1);
        ADD2(r2, r0, r1);
        float2 f = unpack2(r2);
        float zp = f.x + f.y;
        float z  = zp + __shfl_xor_sync(0xFFFFFFFFu, zp, 1);

        if (own) {
            z += p_cur;
            float g = __fdividef(1.0f, 1.0f + __expf(-z));
            float contrib;
            if (rank == 0) {
                float s_old = s_loc[p][j] + s_rem[p][j];
                contrib = s_old * g;
            } else {
                contrib = g * c_cur;
            }
            // publish my contribution for s_{t+1}: local + remote
            s_loc[p ^ 1][j] = contrib;
            st_shared_cluster_f32(p ? pr0 : pr1, contrib);
        }

        __syncthreads();              // s_loc[p^1] visible CTA-wide; orders
        CLUSTER_ARRIVE();             // remote stores before barrier release

        p_cur = p_next; c_cur = c_next;
    }

    CLUSTER_WAIT();                   // final phase: last stores landed
    if (rank == 0 && own)
        g_sfinal[j] = s_loc[T_STEPS & 1][j] + s_rem[T_STEPS & 1][j];
    CLUSTER_ARRIVE();
    CLUSTER_WAIT();
}

// ============================================================
// Phase 3: output head. 1 block, 256 threads.
// ============================================================
__global__ __launch_bounds__(256) void head_kernel(
    const float* __restrict__ W1, const float* __restrict__ b1,
    const float* __restrict__ W2, const float* __restrict__ b2,
    float* __restrict__ out)
{
    __shared__ float s_s[S_DIM], s_h[S_DIM], s_red[256];
    const int tid = threadIdx.x;
    if (tid < S_DIM) s_s[tid] = g_sfinal[tid];
    __syncthreads();

    if (tid < S_DIM) {
        float a = b1[tid];
        for (int k = 0; k < S_DIM; k++) a = fmaf(s_s[k], W1[k * S_DIM + tid], a);
        s_h[tid] = fmaxf(a, 0.0f);
    }
    __syncthreads();
    float h2 = 0.0f;
    if (tid < S_DIM) {
        float a = b2[tid];
        for (int k = 0; k < S_DIM; k++) a = fmaf(s_h[k], W2[k * S_DIM + tid], a);
        h2 = fmaxf(a, 0.0f);
    }
    s_red[tid] = (tid < S_DIM) ? h2 : -1e30f;
    __syncthreads();
    for (int s = 128; s > 0; s >>= 1) {
        if (tid < s) s_red[tid] = fmaxf(s_red[tid], s_red[tid + s]);
        __syncthreads();
    }
    float m = s_red[0];
    __syncthreads();
    s_red[tid] = (tid < S_DIM) ? expf(h2 - m) : 0.0f;
    __syncthreads();
    for (int s = 128; s > 0; s >>= 1) {
        if (tid < s) s_red[tid] += s_red[tid + s];
        __syncthreads();
    }
    float lse = logf(s_red[0]);
    if (tid < S_DIM) out[tid] = h2 - m - lse;
}

// ============================================================
extern "C" void kernel_launch(void* const* d_in, const int* in_sizes, int n_in,
                              void* d_out, int out_size) {
    const float* track  = (const float*)d_in[0];
    const float* state0 = (const float*)d_in[1];
    const float* Wf     = (const float*)d_in[2];
    const float* bf     = (const float*)d_in[3];
    const float* Wi     = (const float*)d_in[4];
    const float* bi     = (const float*)d_in[5];
    const float* Wc     = (const float*)d_in[6];
    const float* bc     = (const float*)d_in[7];
    const float* W1     = (const float*)d_in[8];
    const float* b1     = (const float*)d_in[9];
    const float* W2     = (const float*)d_in[10];
    const float* b2     = (const float*)d_in[11];
    float* out = (float*)d_out;

    dim3 g(T_STEPS / TILE_T, 3);
    pre_kernel<<<g, 256>>>(track, Wf, bf, Wi, bi, Wc, bc);
    scan_kernel<<<2, 416>>>(Wf, Wi, state0);
    head_kernel<<<1, 256>>>(W1, b1, W2, b2, out);
}

// round 13
// speedup vs baseline: 1.7019x; 1.6533x over previous
#include <cuda_runtime.h>
#include <cuda_bf16.h>
#include <math.h>

#define T_STEPS 100000
#define S_DIM   200
#define N_DIM   215

// ---- device scratch (static; no runtime allocation) ----
__device__ float g_pre_f[T_STEPS * S_DIM];
__device__ float g_pre_i[T_STEPS * S_DIM];
__device__ float g_cand [T_STEPS * S_DIM];
__device__ float g_sfinal[S_DIM];

// ---- helpers ----
__device__ __forceinline__ unsigned smem_u32(const void* p) {
    unsigned a;
    asm("{ .reg .u64 t; cvta.to.shared.u64 t, %1; cvt.u32.u64 %0, t; }"
        : "=r"(a) : "l"(p));
    return a;
}
__device__ __forceinline__ unsigned mapa_u32(unsigned a, unsigned rank) {
    unsigned d;
    asm("mapa.shared::cluster.u32 %0, %1, %2;" : "=r"(d) : "r"(a), "r"(rank));
    return d;
}
// remote 8-byte store into the peer CTA's smem (single-copy atomic, aligned 8)
__device__ __forceinline__ void st_shared_cluster_b64(unsigned addr,
                                                      unsigned long long v) {
    asm volatile("st.shared::cluster.b64 [%0], %1;"
                 :: "r"(addr), "l"(v) : "memory");
}
// local volatile smem read (poll target; compiler cannot hoist/cache)
__device__ __forceinline__ unsigned long long ld_volatile_shared_b64(unsigned addr) {
    unsigned long long v;
    asm volatile("ld.volatile.shared.b64 %0, [%1];"
                 : "=l"(v) : "r"(addr) : "memory");
    return v;
}
__device__ __forceinline__ unsigned long long pack2(float x, float y) {
    unsigned long long r;
    asm("mov.b64 %0, {%1, %2};" : "=l"(r) : "f"(x), "f"(y));
    return r;
}
__device__ __forceinline__ float2 unpack2(unsigned long long v) {
    float2 f;
    asm("mov.b64 {%0, %1}, %2;" : "=f"(f.x), "=f"(f.y) : "l"(v));
    return f;
}
__device__ __forceinline__ unsigned long long tag_pack(unsigned tag, float val) {
    unsigned long long r;
    asm("mov.b64 %0, {%1, %2};" : "=l"(r) : "f"(val), "r"(tag));
    return r;  // lo = value, hi = tag
}
#define FMA2(acc, a, b) \
    asm("fma.rn.f32x2 %0, %1, %2, %0;" : "+l"(acc) : "l"(a), "l"(b))
#define ADD2(out, a, b) \
    asm("add.rn.f32x2 %0, %1, %2;" : "=l"(out) : "l"(a), "l"(b))

#define CLUSTER_ARRIVE() \
    asm volatile("barrier.cluster.arrive.aligned;" ::: "memory")
#define CLUSTER_WAIT() \
    asm volatile("barrier.cluster.wait.aligned;" ::: "memory")

// ============================================================
// Phase 1: the three track GEMMs. grid (3125,3), block 256.
// ============================================================
#define TILE_T 32
#define KCHUNK 43   // 5*43 = 215

__global__ __launch_bounds__(256) void pre_kernel(
    const float* __restrict__ track,
    const float* __restrict__ Wf, const float* __restrict__ bf,
    const float* __restrict__ Wi, const float* __restrict__ bi,
    const float* __restrict__ Wc, const float* __restrict__ bc)
{
    __shared__ float sW[KCHUNK * S_DIM];
    __shared__ float sT[TILE_T * KCHUNK];
    const int mat = blockIdx.y;
    const int t0  = blockIdx.x * TILE_T;
    const int tid = threadIdx.x;
    const float* W   = (mat == 0) ? Wf : (mat == 1) ? Wi : Wc;
    const float* bia = (mat == 0) ? bf : (mat == 1) ? bi : bc;
    float* out       = (mat == 0) ? g_pre_f : (mat == 1) ? g_pre_i : g_cand;

    float acc[TILE_T];
    #pragma unroll
    for (int i = 0; i < TILE_T; i++) acc[i] = 0.0f;

    for (int c = 0; c < 5; c++) {
        const int k0 = c * KCHUNK;
        for (int idx = tid; idx < KCHUNK * S_DIM; idx += 256) {
            int r = idx / S_DIM, col = idx - r * S_DIM;
            sW[idx] = W[(k0 + r) * S_DIM + col];
        }
        for (int idx = tid; idx < TILE_T * KCHUNK; idx += 256) {
            int tt = idx / KCHUNK, kk = idx - tt * KCHUNK;
            sT[idx] = track[(t0 + tt) * N_DIM + k0 + kk];
        }
        __syncthreads();
        if (tid < S_DIM) {
            for (int kk = 0; kk < KCHUNK; kk++) {
                float wv = sW[kk * S_DIM + tid];
                #pragma unroll
                for (int tt = 0; tt < TILE_T; tt++)
                    acc[tt] = fmaf(sT[tt * KCHUNK + kk], wv, acc[tt]);
            }
        }
        __syncthreads();
    }
    if (tid < S_DIM) {
        float bv = bia[tid];
        #pragma unroll 4
        for (int tt = 0; tt < TILE_T; tt++) {
            float v = acc[tt] + bv;
            if (mat == 2) v = tanhf(v);
            out[(t0 + tt) * S_DIM + tid] = v;
        }
    }
}

// ============================================================
// Phase 2: sequential scan. 2-CTA cluster, 416 threads/CTA.
// Exchange: producer pushes ONE tagged b64 packet {tag=t+1,val}
// into the peer's inbox slot [t&1][j] via st.shared::cluster
// (single-copy atomic -> data is its own flag). Consumer polls
// its OWN smem slot with ld.volatile.shared (29-cyc granularity).
// NO cluster barrier / mbarrier / fence in the loop; one local
// __syncthreads per step for state assembly. Tags are monotonic;
// parity double-buffer + mutual data dependency (skew <= 1 step)
// make slot reuse race-free.
// rank0: u = s_old * sigmoid(pre_f + s@Wf_s)
// rank1: v = sigmoid(pre_i + s@Wi_s) * cand
// s_new = u + v.
// ============================================================
__global__ void __cluster_dims__(2, 1, 1) __launch_bounds__(416, 1)
scan_kernel(const float* __restrict__ Wf, const float* __restrict__ Wi,
            const float* __restrict__ state0)
{
    __shared__ __align__(16) float s_state[S_DIM];
    __shared__ __align__(16) unsigned long long s_inbox[2][S_DIM];

    const int tid = threadIdx.x;
    unsigned rank;
    asm("mov.u32 %0, %%cluster_ctarank;" : "=r"(rank));
    const unsigned peerR = rank ^ 1u;

    const bool act = (tid < 400);
    const int  j   = act ? (tid >> 1) : 0;   // output column
    const int  h   = tid & 1;                // k-half
    const bool own = act && (h == 0);

    // ---- load this CTA's recurrent matrix into registers ----
    const float* W = (rank == 0) ? Wf : Wi;  // rows [215,415) = recurrent part
    const int kbase = N_DIM + h * 100;
    unsigned long long w[50];
    #pragma unroll
    for (int i = 0; i < 50; i++) {
        float a = act ? W[(kbase + 2 * i    ) * S_DIM + j] : 0.0f;
        float b = act ? W[(kbase + 2 * i + 1) * S_DIM + j] : 0.0f;
        w[i] = pack2(a, b);
    }

    // init: state + zero-tagged inbox slots (own CTA's inbox)
    if (own) {
        s_state[j] = state0[j];
        s_inbox[0][j] = 0ull;
        s_inbox[1][j] = 0ull;
    }
    __syncthreads();
    CLUSTER_ARRIVE();    // one-time: init visible cluster-wide before any push
    CLUSTER_WAIT();

    // remote addresses of MY column's slot in the PEER's inbox (both parities)
    const unsigned pi0 = mapa_u32(smem_u32(&s_inbox[0][own ? j : 0]), peerR);
    const unsigned pi1 = mapa_u32(smem_u32(&s_inbox[1][own ? j : 0]), peerR);
    // local addresses of my own inbox slot (poll targets)
    const unsigned li0 = smem_u32(&s_inbox[0][own ? j : 0]);
    const unsigned li1 = smem_u32(&s_inbox[1][own ? j : 0]);

    const float* pre = (rank == 0) ? g_pre_f : g_pre_i;
    float p_cur = 0.0f, c_cur = 0.0f;
    if (own) {
        p_cur = __ldcg(pre + j);
        if (rank == 1) c_cur = __ldcg(g_cand + j);
    }

    for (int t = 0; t < T_STEPS; t++) {
        const int b = t & 1;

        // prefetch next step's streams (hides DRAM latency)
        float p_next = 0.0f, c_next = 0.0f;
        if (own) {
            int tn = (t + 1 < T_STEPS) ? (t + 1) : (T_STEPS - 1);
            p_next = __ldcg(pre + tn * S_DIM + j);
            if (rank == 1) c_next = __ldcg(g_cand + tn * S_DIM + j);
        }

        // ---- matvec: 100 MACs/thread as 50 packed f32x2 FMAs ----
        unsigned long long a0 = 0ull, a1 = 0ull;
        const ulonglong2* s4 = (const ulonglong2*)s_state + h * 25;
        #pragma unroll
        for (int i = 0; i < 25; i++) {
            ulonglong2 sv = s4[i];
            FMA2(a0, w[2 * i    ], sv.x);
            FMA2(a1, w[2 * i + 1], sv.y);
        }
        unsigned long long r01;
        ADD2(r01, a0, a1);
        float2 f = unpack2(r01);
        float zp = f.x + f.y;
        float z  = zp + __shfl_xor_sync(0xFFFFFFFFu, zp, 1);

        if (own) {
            z += p_cur;
            float g = __fdividef(1.0f, 1.0f + __expf(-z));
            float contrib = (rank == 0) ? (s_state[j] * g) : (g * c_cur);

            // push tagged packet into the peer's inbox (data = its own flag)
            const unsigned tag = (unsigned)(t + 1);
            st_shared_cluster_b64(b ? pi1 : pi0, tag_pack(tag, contrib));

            // poll MY OWN smem slot for the peer's packet (29-cyc granularity)
            const unsigned slot = b ? li1 : li0;
            unsigned long long pkt = ld_volatile_shared_b64(slot);
            while ((unsigned)(pkt >> 32) != tag)
                pkt = ld_volatile_shared_b64(slot);
            float pv = __uint_as_float((unsigned)pkt);

            s_state[j] = contrib + pv;
        }
        __syncthreads();

        p_cur = p_next; c_cur = c_next;
    }

    if (rank == 0 && own) g_sfinal[j] = s_state[j];
    // exit sync: no CTA may die while its peer might still push into it
    CLUSTER_ARRIVE();
    CLUSTER_WAIT();
}

// ============================================================
// Phase 3: output head. 1 block, 256 threads.
// ============================================================
__global__ __launch_bounds__(256) void head_kernel(
    const float* __restrict__ W1, const float* __restrict__ b1,
    const float* __restrict__ W2, const float* __restrict__ b2,
    float* __restrict__ out)
{
    __shared__ float s_s[S_DIM], s_h[S_DIM], s_red[256];
    const int tid = threadIdx.x;
    if (tid < S_DIM) s_s[tid] = g_sfinal[tid];
    __syncthreads();

    if (tid < S_DIM) {
        float a = b1[tid];
        for (int k = 0; k < S_DIM; k++) a = fmaf(s_s[k], W1[k * S_DIM + tid], a);
        s_h[tid] = fmaxf(a, 0.0f);
    }
    __syncthreads();
    float h2 = 0.0f;
    if (tid < S_DIM) {
        float a = b2[tid];
        for (int k = 0; k < S_DIM; k++) a = fmaf(s_h[k], W2[k * S_DIM + tid], a);
        h2 = fmaxf(a, 0.0f);
    }
    s_red[tid] = (tid < S_DIM) ? h2 : -1e30f;
    __syncthreads();
    for (int s = 128; s > 0; s >>= 1) {
        if (tid < s) s_red[tid] = fmaxf(s_red[tid], s_red[tid + s]);
        __syncthreads();
    }
    float m = s_red[0];
    __syncthreads();
    s_red[tid] = (tid < S_DIM) ? expf(h2 - m) : 0.0f;
    __syncthreads();
    for (int s = 128; s > 0; s >>= 1) {
        if (tid < s) s_red[tid] += s_red[tid + s];
        __syncthreads();
    }
    float lse = logf(s_red[0]);
    if (tid < S_DIM) out[tid] = h2 - m - lse;
}

// ============================================================
extern "C" void kernel_launch(void* const* d_in, const int* in_sizes, int n_in,
                              void* d_out, int out_size) {
    const float* track  = (const float*)d_in[0];
    const float* state0 = (const float*)d_in[1];
    const float* Wf     = (const float*)d_in[2];
    const float* bf     = (const float*)d_in[3];
    const float* Wi     = (const float*)d_in[4];
    const float* bi     = (const float*)d_in[5];
    const float* Wc     = (const float*)d_in[6];
    const float* bc     = (const float*)d_in[7];
    const float* W1     = (const float*)d_in[8];
    const float* b1     = (const float*)d_in[9];
    const float* W2     = (const float*)d_in[10];
    const float* b2     = (const float*)d_in[11];
    float* out = (float*)d_out;

    dim3 g(T_STEPS / TILE_T, 3);
    pre_kernel<<<g, 256>>>(track, Wf, bf, Wi, bi, Wc, bc);
    scan_kernel<<<2, 416>>>(Wf, Wi, state0);
    head_kernel<<<1, 256>>>(W1, b1, W2, b2, out);
}